// round 3
// baseline (speedup 1.0000x reference)
#include <cuda_runtime.h>
#include <cstdint>

// ---------------- problem constants ----------------
#define BS    32
#define SL    2048
#define MEMD  2048                // K of the big GEMM
#define HID   1024                // N of the big GEMM
#define IND   1024
#define MTOT  (BS * SL)           // 65536 GEMM rows (M)
#define OUT_SCORE_OFF (BS * MEMD) // context [32,2048] first, then score [32,2048]

// ---------------- GEMM tiling ----------------
#define TM       128
#define TN       128
#define KC       32               // K elems per stage (128 B rows)
#define NSTAGES  4
#define NKITER   (MEMD / KC)      // 64
#define STG_FLT  (TM * KC + TN * KC)   // 8192 floats = 32 KB per stage
#define SMEM_GEMM (NSTAGES * STG_FLT * 4)  // 131072

// ---------------- device scratch (static, no allocations) ----------------
__device__ float g_W2T[HID * MEMD];   // W2 transposed: [h][d], K-major
__device__ float g_hx[BS * HID];      // x@W1 + b1 + b2
__device__ float g_logits[MTOT];

// ---------------- helpers ----------------
__device__ __forceinline__ uint32_t smem_u32(const void* p) {
    uint32_t a;
    asm("{ .reg .u64 t; cvta.to.shared.u64 t, %1; cvt.u32.u64 %0, t; }" : "=r"(a) : "l"(p));
    return a;
}
#define CP_ASYNC16(dst, src) \
    asm volatile("cp.async.cg.shared.global [%0], [%1], 16;" :: "r"(dst), "l"(src) : "memory")
#define CP_COMMIT() asm volatile("cp.async.commit_group;" ::: "memory")
#define CP_WAIT2()  asm volatile("cp.async.wait_group 2;" ::: "memory")

// swizzled float index within a [rows][32] tile: 16B chunk id XORed with row&7
__device__ __forceinline__ int swz(int r, int c) {
    return r * 32 + ((c & 3) | ((((c >> 2) ^ (r & 7)) & 7) << 2));
}

// tf32 MMA, fp32 accumulate (legacy tensor path, valid on sm_100 base target)
__device__ __forceinline__ void mma_tf32(float* c, const uint32_t* a, const uint32_t* b) {
    asm volatile(
        "mma.sync.aligned.m16n8k8.row.col.f32.tf32.tf32.f32 "
        "{%0,%1,%2,%3}, {%4,%5,%6,%7}, {%8,%9}, {%0,%1,%2,%3};"
        : "+f"(c[0]), "+f"(c[1]), "+f"(c[2]), "+f"(c[3])
        : "r"(a[0]), "r"(a[1]), "r"(a[2]), "r"(a[3]), "r"(b[0]), "r"(b[1]));
}

// ============================================================
// Stage loader: A [128 x 32] + B [128 x 32] fp32, swizzled, via cp.async
// ============================================================
__device__ __forceinline__ void load_stage(
    int tid, uint32_t sa, uint32_t sb,
    const float* __restrict__ Ag, const float* __restrict__ Bg)
{
    #pragma unroll
    for (int o = tid; o < TM * 8; o += 256) {     // 8 chunks of 16B per row
        int r = o >> 3, ch = o & 7;
        uint32_t dst = sa + (uint32_t)(r * 32 + ((ch ^ (r & 7)) << 2)) * 4;
        CP_ASYNC16(dst, Ag + (long)r * MEMD + ch * 4);
    }
    #pragma unroll
    for (int o = tid; o < TN * 8; o += 256) {
        int r = o >> 3, ch = o & 7;
        uint32_t dst = sb + (uint32_t)(r * 32 + ((ch ^ (r & 7)) << 2)) * 4;
        CP_ASYNC16(dst, Bg + (long)r * MEMD + ch * 4);
    }
    CP_COMMIT();
}

// ============================================================
// GEMM (memory @ W2T) fused with tanh/v-dot reduction -> logits
// grid (MTOT/TM = 512, HID/TN = 8), 256 threads
// ============================================================
__global__ void __launch_bounds__(256, 1) gemm_score_kernel(
    const float* __restrict__ mem, const float* __restrict__ v)
{
    extern __shared__ float dsm[];
    __shared__ float hxs[TN], vt[TN];

    const int tid  = threadIdx.x;
    const int wid  = tid >> 5, lane = tid & 31;
    const int wm   = wid >> 2, wn = wid & 3;       // 2 x 4 warp grid
    const int tg   = lane >> 2, tig = lane & 3;
    const long g0  = (long)blockIdx.x * TM;        // global row base
    const int  n0  = blockIdx.y * TN;              // global h base
    const int  b   = blockIdx.x >> 4;              // 16 M-tiles per batch (SL/TM)

    if (tid < TN) {
        hxs[tid] = g_hx[b * HID + n0 + tid];
        vt[tid]  = v[n0 + tid];
    }

    const uint32_t sbase = smem_u32(dsm);
    const float* Ag = mem + g0 * MEMD;
    const float* Bg = g_W2T + (long)n0 * MEMD;

    float acc[4][4][4];
    #pragma unroll
    for (int i = 0; i < 4; i++)
        #pragma unroll
        for (int j = 0; j < 4; j++)
            #pragma unroll
            for (int k = 0; k < 4; k++) acc[i][j][k] = 0.f;

    // prologue: stages 0..2
    #pragma unroll
    for (int s = 0; s < 3; s++) {
        uint32_t st = sbase + (uint32_t)s * STG_FLT * 4;
        load_stage(tid, st, st + TM * KC * 4, Ag + s * KC, Bg + s * KC);
    }

    for (int it = 0; it < NKITER; it++) {
        CP_WAIT2();
        __syncthreads();

        // prefetch stage it+3 (or empty commit to keep wait_group counting valid)
        if (it + 3 < NKITER) {
            int buf = (it + 3) & 3;
            uint32_t st = sbase + (uint32_t)buf * STG_FLT * 4;
            load_stage(tid, st, st + TM * KC * 4, Ag + (it + 3) * KC, Bg + (it + 3) * KC);
        } else {
            CP_COMMIT();
        }

        const uint32_t sa = sbase + (uint32_t)(it & 3) * STG_FLT * 4;
        const uint32_t sb = sa + TM * KC * 4;
        const float* fA = (const float*)dsm + (it & 3) * STG_FLT;
        const float* fB = fA + TM * KC;

        #pragma unroll
        for (int ks = 0; ks < 4; ks++) {           // 4 x k8 per stage
            uint32_t a[4][4], bfr[4][2];
            const int k0 = ks * 8;
            #pragma unroll
            for (int mi = 0; mi < 4; mi++) {
                int r0 = wm * 64 + mi * 16 + tg;
                a[mi][0] = __float_as_uint(fA[swz(r0,     k0 + tig)]);
                a[mi][1] = __float_as_uint(fA[swz(r0 + 8, k0 + tig)]);
                a[mi][2] = __float_as_uint(fA[swz(r0,     k0 + 4 + tig)]);
                a[mi][3] = __float_as_uint(fA[swz(r0 + 8, k0 + 4 + tig)]);
            }
            #pragma unroll
            for (int ni = 0; ni < 4; ni++) {
                int nr = wn * 32 + ni * 8 + tg;
                bfr[ni][0] = __float_as_uint(fB[swz(nr, k0 + tig)]);
                bfr[ni][1] = __float_as_uint(fB[swz(nr, k0 + 4 + tig)]);
            }
            #pragma unroll
            for (int mi = 0; mi < 4; mi++)
                #pragma unroll
                for (int ni = 0; ni < 4; ni++)
                    mma_tf32(acc[mi][ni], a[mi], bfr[ni]);
        }
        (void)sa; (void)sb;
    }
    __syncthreads();

    // Epilogue: partial logit = sum_h v[h] * tanh(hx[h] + hm[h]) over this CTA's 128 h
    #pragma unroll
    for (int mi = 0; mi < 4; mi++) {
        float p0 = 0.f, p1 = 0.f;
        #pragma unroll
        for (int ni = 0; ni < 4; ni++) {
            int col = wn * 32 + ni * 8 + tig * 2;
            float v0 = vt[col], v1 = vt[col + 1];
            float h0 = hxs[col], h1 = hxs[col + 1];
            p0 += v0 * tanhf(h0 + acc[mi][ni][0]) + v1 * tanhf(h1 + acc[mi][ni][1]);
            p1 += v0 * tanhf(h0 + acc[mi][ni][2]) + v1 * tanhf(h1 + acc[mi][ni][3]);
        }
        p0 += __shfl_xor_sync(0xFFFFFFFFu, p0, 1);
        p0 += __shfl_xor_sync(0xFFFFFFFFu, p0, 2);
        p1 += __shfl_xor_sync(0xFFFFFFFFu, p1, 1);
        p1 += __shfl_xor_sync(0xFFFFFFFFu, p1, 2);
        if (tig == 0) {
            long r = g0 + wm * 64 + mi * 16 + tg;
            atomicAdd(&g_logits[r],     p0);
            atomicAdd(&g_logits[r + 8], p1);
        }
    }
}

// ============================================================
// Small kernels
// ============================================================
__global__ void zero_logits_kernel() {
    g_logits[blockIdx.x * 256 + threadIdx.x] = 0.f;
}

__global__ void transpose_w2_kernel(const float* __restrict__ W2) {
    __shared__ float t[32][33];
    int d0 = blockIdx.x * 32, h0 = blockIdx.y * 32;
    int tx = threadIdx.x, ty = threadIdx.y;
    #pragma unroll
    for (int i = 0; i < 32; i += 8)
        t[ty + i][tx] = W2[(long)(d0 + ty + i) * HID + h0 + tx];
    __syncthreads();
    #pragma unroll
    for (int i = 0; i < 32; i += 8)
        g_W2T[(long)(h0 + ty + i) * MEMD + d0 + tx] = t[tx][ty + i];
}

__global__ void __launch_bounds__(256) hx_kernel(
    const float* __restrict__ x, const float* __restrict__ W1,
    const float* __restrict__ b1, const float* __restrict__ b2)
{
    int h = blockIdx.x * 256 + threadIdx.x;
    int b = blockIdx.y;
    const float* xr = x + b * IND;
    float acc = 0.f;
    #pragma unroll 8
    for (int d = 0; d < IND; d++)
        acc += xr[d] * W1[(long)d * HID + h];
    g_hx[b * HID + h] = acc + b1[h] + b2[h];
}

__global__ void __launch_bounds__(256) softmax_kernel(float* __restrict__ out) {
    __shared__ float buf[SL];
    __shared__ float red[256];
    const int b = blockIdx.x, tid = threadIdx.x;
    float m = -1e30f;
    for (int s = tid; s < SL; s += 256) {
        float l = g_logits[b * SL + s];
        buf[s] = l;
        m = fmaxf(m, l);
    }
    red[tid] = m; __syncthreads();
    for (int o = 128; o > 0; o >>= 1) {
        if (tid < o) red[tid] = fmaxf(red[tid], red[tid + o]);
        __syncthreads();
    }
    m = red[0]; __syncthreads();
    float sum = 0.f;
    for (int s = tid; s < SL; s += 256) {
        float e = __expf(buf[s] - m);
        buf[s] = e;
        sum += e;
    }
    red[tid] = sum; __syncthreads();
    for (int o = 128; o > 0; o >>= 1) {
        if (tid < o) red[tid] += red[tid + o];
        __syncthreads();
    }
    float inv = 1.f / red[0];
    for (int s = tid; s < SL; s += 256)
        out[OUT_SCORE_OFF + b * SL + s] = buf[s] * inv;
}

__global__ void __launch_bounds__(256) context_kernel(
    const float* __restrict__ mem, float* __restrict__ out)
{
    const int b = blockIdx.y;
    const int d = blockIdx.x * 256 + threadIdx.x;
    const float* sc = out + OUT_SCORE_OFF + b * SL;
    const float* mb = mem + (long)b * SL * MEMD + d;
    float acc = 0.f;
    #pragma unroll 4
    for (int s = 0; s < SL; s++)
        acc += sc[s] * mb[(long)s * MEMD];
    out[b * MEMD + d] = acc;
}

// ============================================================
// Launch
// ============================================================
extern "C" void kernel_launch(void* const* d_in, const int* in_sizes, int n_in,
                              void* d_out, int out_size)
{
    const float* x      = (const float*)d_in[0];
    const float* memory = (const float*)d_in[1];
    const float* W1     = (const float*)d_in[2];
    const float* b1     = (const float*)d_in[3];
    const float* W2     = (const float*)d_in[4];
    const float* b2     = (const float*)d_in[5];
    const float* v      = (const float*)d_in[6];
    // d_in[7] = bv: cancels under softmax (shift invariance), unused.
    float* out = (float*)d_out;

    cudaFuncSetAttribute(gemm_score_kernel,
                         cudaFuncAttributeMaxDynamicSharedMemorySize, SMEM_GEMM);

    zero_logits_kernel<<<MTOT / 256, 256>>>();
    transpose_w2_kernel<<<dim3(MEMD / 32, HID / 32), dim3(32, 8)>>>(W2);
    hx_kernel<<<dim3(HID / 256, BS), 256>>>(x, W1, b1, b2);
    gemm_score_kernel<<<dim3(MTOT / TM, HID / TN), 256, SMEM_GEMM>>>(memory, v);
    softmax_kernel<<<BS, 256>>>(out);
    context_kernel<<<dim3(MEMD / 256, BS), 256>>>(memory, out);
}